// round 3
// baseline (speedup 1.0000x reference)
#include <cuda_runtime.h>
#include <cuda_bf16.h>
#include <cstdint>
#include <cstddef>

#define NNODES 100000
#define CAP 2048
#define GRID 148
#define TPB 512

// ---- scratch (device globals; no allocation allowed) ----------------------
__device__ int           g_deg[NNODES];
__device__ float         g_dinv[NNODES];
__device__ float         g_s[NNODES];
__device__ unsigned char g_needed[NNODES];
__device__ int           g_last_src[CAP];
__device__ int           g_count;
__device__ int           g_mode64;
__device__ unsigned int           g_bar_count;
__device__ volatile unsigned int  g_bar_gen;

// ---- software grid barrier (all GRID blocks are co-resident) --------------
__device__ __forceinline__ void grid_barrier() {
    __syncthreads();
    if (threadIdx.x == 0) {
        __threadfence();                       // publish my phase's writes
        unsigned gen = g_bar_gen;
        unsigned arrived = atomicAdd(&g_bar_count, 1u);
        if (arrived == GRID - 1) {
            g_bar_count = 0u;
            __threadfence();
            g_bar_gen = gen + 1u;              // release
        } else {
            while (g_bar_gen == gen) { }       // volatile spin
        }
        __threadfence();                       // acquire others' writes
    }
    __syncthreads();
}

// ---------------------------------------------------------------------------
__global__ void __launch_bounds__(TPB, 1)
gcn_fused_kernel(const void* __restrict__ eidx,
                 const float* __restrict__ x,
                 const float* __restrict__ W1, const float* __restrict__ b1,
                 const float* __restrict__ W2, const float* __restrict__ b2,
                 const float* __restrict__ Wfc, const float* __restrict__ bfc,
                 float* __restrict__ out, int E) {
    const int tid      = blockIdx.x * TPB + threadIdx.x;
    const int nthreads = GRID * TPB;

    // ================= Phase 0: zero scratch + dtype detect =================
    for (int n = tid; n < NNODES; n += nthreads) {
        g_deg[n] = 0;
        g_s[n] = 0.0f;
        g_needed[n] = 0;
    }
    if (tid == 0) {
        g_count = 0;
        // int64 little-endian: every odd 32-bit word of values < 2^31 is 0.
        const unsigned int* w = (const unsigned int*)eidx;
        int all0 = 1;
        #pragma unroll
        for (int i = 0; i < 32; i++)
            if (w[2 * i + 1] != 0u) all0 = 0;
        g_mode64 = all0;
    }
    grid_barrier();

    const int mode = g_mode64;

    // ================= Phase 1: in-degree + collect edges into node N-1 ====
    if (mode) {
        const long long* __restrict__ srcp = (const long long*)eidx;
        const long long* __restrict__ dstp = srcp + E;
        int nv = E >> 1;                                   // 2 edges / 16B load
        const ulonglong2* __restrict__ dv = (const ulonglong2*)dstp;
        for (int i = tid; i < nv; i += nthreads) {
            ulonglong2 d2 = dv[i];
            int d0 = (int)d2.x, d1 = (int)d2.y;
            atomicAdd(&g_deg[d0], 1);
            atomicAdd(&g_deg[d1], 1);
            if (d0 == NNODES - 1) {
                int pos = atomicAdd(&g_count, 1);
                if (pos < CAP) g_last_src[pos] = (int)srcp[2 * i];
            }
            if (d1 == NNODES - 1) {
                int pos = atomicAdd(&g_count, 1);
                if (pos < CAP) g_last_src[pos] = (int)srcp[2 * i + 1];
            }
        }
        for (int e = (nv << 1) + tid; e < E; e += nthreads) {
            int d = (int)dstp[e];
            atomicAdd(&g_deg[d], 1);
            if (d == NNODES - 1) {
                int pos = atomicAdd(&g_count, 1);
                if (pos < CAP) g_last_src[pos] = (int)srcp[e];
            }
        }
    } else {
        const int* __restrict__ srcp = (const int*)eidx;
        const int* __restrict__ dstp = srcp + E;
        int nv = (((unsigned long long)(size_t)dstp & 15ull) == 0ull) ? (E >> 2) : 0;
        const int4* __restrict__ dv = (const int4*)dstp;
        for (int i = tid; i < nv; i += nthreads) {
            int4 d4 = dv[i];
            atomicAdd(&g_deg[d4.x], 1);
            atomicAdd(&g_deg[d4.y], 1);
            atomicAdd(&g_deg[d4.z], 1);
            atomicAdd(&g_deg[d4.w], 1);
            if (d4.x == NNODES - 1) { int p = atomicAdd(&g_count, 1); if (p < CAP) g_last_src[p] = srcp[4 * i + 0]; }
            if (d4.y == NNODES - 1) { int p = atomicAdd(&g_count, 1); if (p < CAP) g_last_src[p] = srcp[4 * i + 1]; }
            if (d4.z == NNODES - 1) { int p = atomicAdd(&g_count, 1); if (p < CAP) g_last_src[p] = srcp[4 * i + 2]; }
            if (d4.w == NNODES - 1) { int p = atomicAdd(&g_count, 1); if (p < CAP) g_last_src[p] = srcp[4 * i + 3]; }
        }
        for (int e = (nv << 2) + tid; e < E; e += nthreads) {
            int d = dstp[e];
            atomicAdd(&g_deg[d], 1);
            if (d == NNODES - 1) { int p = atomicAdd(&g_count, 1); if (p < CAP) g_last_src[p] = srcp[e]; }
        }
    }
    grid_barrier();

    // ================= Phase 2: dinv + mark needed nodes ====================
    for (int n = tid; n < NNODES; n += nthreads)
        g_dinv[n] = rsqrtf((float)(g_deg[n] + 1));          // +1 self-loop
    if (blockIdx.x == 0) {
        int c = g_count; if (c > CAP) c = CAP;
        for (int k = threadIdx.x; k < c; k += TPB)
            g_needed[g_last_src[k]] = 1;
        if (threadIdx.x == 0) g_needed[NNODES - 1] = 1;
    }
    grid_barrier();

    // ================= Phase 3: layer-1 scalar gather (needed dsts only) ===
    if (mode) {
        const long long* __restrict__ srcp = (const long long*)eidx;
        const long long* __restrict__ dstp = srcp + E;
        int nv = E >> 1;
        const ulonglong2* __restrict__ dv = (const ulonglong2*)dstp;
        for (int i = tid; i < nv; i += nthreads) {
            ulonglong2 d2 = dv[i];
            int d0 = (int)d2.x, d1 = (int)d2.y;
            if (g_needed[d0]) {
                int s = (int)srcp[2 * i];
                atomicAdd(&g_s[d0], x[s] * g_dinv[s] * g_dinv[d0]);
            }
            if (g_needed[d1]) {
                int s = (int)srcp[2 * i + 1];
                atomicAdd(&g_s[d1], x[s] * g_dinv[s] * g_dinv[d1]);
            }
        }
        for (int e = (nv << 1) + tid; e < E; e += nthreads) {
            int d = (int)dstp[e];
            if (g_needed[d]) {
                int s = (int)srcp[e];
                atomicAdd(&g_s[d], x[s] * g_dinv[s] * g_dinv[d]);
            }
        }
    } else {
        const int* __restrict__ srcp = (const int*)eidx;
        const int* __restrict__ dstp = srcp + E;
        int nv = (((unsigned long long)(size_t)dstp & 15ull) == 0ull) ? (E >> 2) : 0;
        const int4* __restrict__ dv = (const int4*)dstp;
        for (int i = tid; i < nv; i += nthreads) {
            int4 d4 = dv[i];
            if (g_needed[d4.x]) { int s = srcp[4 * i + 0]; atomicAdd(&g_s[d4.x], x[s] * g_dinv[s] * g_dinv[d4.x]); }
            if (g_needed[d4.y]) { int s = srcp[4 * i + 1]; atomicAdd(&g_s[d4.y], x[s] * g_dinv[s] * g_dinv[d4.y]); }
            if (g_needed[d4.z]) { int s = srcp[4 * i + 2]; atomicAdd(&g_s[d4.z], x[s] * g_dinv[s] * g_dinv[d4.z]); }
            if (g_needed[d4.w]) { int s = srcp[4 * i + 3]; atomicAdd(&g_s[d4.w], x[s] * g_dinv[s] * g_dinv[d4.w]); }
        }
        for (int e = (nv << 2) + tid; e < E; e += nthreads) {
            int d = dstp[e];
            if (g_needed[d]) { int s = srcp[e]; atomicAdd(&g_s[d], x[s] * g_dinv[s] * g_dinv[d]); }
        }
    }
    grid_barrier();

    // ================= Phase 4: layer-2 @ node N-1 + fc head (1 warp) ======
    if (blockIdx.x == 0 && threadIdx.x < 32) {
        int lane = threadIdx.x;
        __shared__ float sW1[16], sb1[16], sW2[128], sb2[8], sWfc[8];
        if (lane < 16) { sW1[lane] = W1[lane]; sb1[lane] = b1[lane]; }
        if (lane < 8)  { sb2[lane] = b2[lane]; sWfc[lane] = Wfc[lane]; }
        for (int k = lane; k < 128; k += 32) sW2[k] = W2[k];
        __syncwarp();

        const float dinvL = g_dinv[NNODES - 1];
        int c = g_count; if (c > CAP) c = CAP;

        float agg[8];
        #pragma unroll
        for (int j = 0; j < 8; j++) agg[j] = 0.0f;

        // k in [0, c): real edges into N-1; k == c: appended self-loop.
        for (int k = lane; k <= c; k += 32) {
            int u = (k == c) ? (NNODES - 1) : g_last_src[k];
            float du = g_dinv[u];
            float norm = du * dinvL;
            float su = g_s[u] + x[u] * du * du;   // layer-1 agg incl. self-loop
            float h1[16];
            #pragma unroll
            for (int j = 0; j < 16; j++)
                h1[j] = fmaxf(fmaf(su, sW1[j], sb1[j]), 0.0f);
            #pragma unroll
            for (int j = 0; j < 8; j++) {
                float v = 0.0f;
                #pragma unroll
                for (int t = 0; t < 16; t++) v = fmaf(h1[t], sW2[t * 8 + j], v);
                agg[j] = fmaf(v, norm, agg[j]);
            }
        }
        #pragma unroll
        for (int off = 16; off > 0; off >>= 1) {
            #pragma unroll
            for (int j = 0; j < 8; j++)
                agg[j] += __shfl_down_sync(0xffffffff, agg[j], off);
        }
        if (lane == 0) {
            float o = bfc[0];
            #pragma unroll
            for (int j = 0; j < 8; j++) {
                float h2 = fmaxf(agg[j] + sb2[j], 0.0f);
                o = fmaf(h2, sWfc[j], o);
            }
            out[0] = o;
        }
    }
}

// ---------------------------------------------------------------------------
extern "C" void kernel_launch(void* const* d_in, const int* in_sizes, int n_in,
                              void* d_out, int out_size) {
    const float* x    = (const float*)d_in[0];
    const void*  eidx = d_in[1];
    const float* W1   = (const float*)d_in[2];
    const float* b1   = (const float*)d_in[3];
    const float* W2   = (const float*)d_in[4];
    const float* b2   = (const float*)d_in[5];
    const float* Wfc  = (const float*)d_in[6];
    const float* bfc  = (const float*)d_in[7];
    float* out = (float*)d_out;

    int E = in_sizes[1] / 2;

    gcn_fused_kernel<<<GRID, TPB>>>(eidx, x, W1, b1, W2, b2, Wfc, bfc, out, E);
}

// round 4
// speedup vs baseline: 1.4011x; 1.4011x over previous
#include <cuda_runtime.h>
#include <cuda_bf16.h>
#include <cstdint>
#include <cstddef>

#define NNODES 100000
#define NLAST  (NNODES - 1)
#define CAP1   4096
#define CAP2   32768
#define GRID   148
#define TPB    1024

// ---- scratch (device globals; no allocation allowed) ----------------------
__device__ int           g_deg[NNODES];
__device__ float         g_s[NNODES];
__device__ unsigned char g_needed[NNODES];    // layer-1 dsts we must aggregate
__device__ unsigned char g_need_deg[NNODES];  // nodes whose degree is consumed
__device__ int           g_s1[CAP1];          // srcs of edges into node N-1
__device__ int           g_pair_src[CAP2];    // edges into needed set
__device__ int           g_pair_dst[CAP2];
__device__ int           g_count1;
__device__ int           g_count2;
__device__ int           g_mode64;
__device__ unsigned int           g_bar_count;
__device__ volatile unsigned int  g_bar_gen;

// ---- software grid barrier (GRID blocks, 1/SM, guaranteed co-resident) ----
__device__ __forceinline__ void grid_barrier() {
    __syncthreads();
    if (threadIdx.x == 0) {
        __threadfence();
        unsigned gen = g_bar_gen;
        unsigned arrived = atomicAdd(&g_bar_count, 1u);
        if (arrived == GRID - 1) {
            g_bar_count = 0u;
            __threadfence();
            g_bar_gen = gen + 1u;
        } else {
            while (g_bar_gen == gen) { }
        }
        __threadfence();
    }
    __syncthreads();
}

// ---------------------------------------------------------------------------
__global__ void __launch_bounds__(TPB, 1)
gcn_fused_kernel(const void* __restrict__ eidx,
                 const float* __restrict__ x,
                 const float* __restrict__ W1, const float* __restrict__ b1,
                 const float* __restrict__ W2, const float* __restrict__ b2,
                 const float* __restrict__ Wfc, const float* __restrict__ bfc,
                 float* __restrict__ out, int E) {
    const int tid      = blockIdx.x * TPB + threadIdx.x;
    const int nthreads = GRID * TPB;

    // ================= P0: zero scratch + dtype detect ======================
    for (int n = tid; n < NNODES; n += nthreads) {
        g_deg[n] = 0;
        g_s[n] = 0.0f;
        g_needed[n] = 0;
        g_need_deg[n] = 0;
    }
    if (tid == 0) {
        g_count1 = 0;
        g_count2 = 0;
        // int64 little-endian: odd 32-bit words of values < 2^31 are all 0.
        const unsigned int* w = (const unsigned int*)eidx;
        int all0 = 1;
        #pragma unroll
        for (int i = 0; i < 32; i++)
            if (w[2 * i + 1] != 0u) all0 = 0;
        g_mode64 = all0;
    }
    grid_barrier();

    const int mode = g_mode64;

    // ================= P1: pure scan — edges with dst == N-1 ===============
    if (mode) {
        const long long* __restrict__ srcp = (const long long*)eidx;
        const long long* __restrict__ dstp = srcp + E;
        int nv = E >> 1;
        const ulonglong2* __restrict__ dv = (const ulonglong2*)dstp;
        for (int i = tid; i < nv; i += nthreads) {
            ulonglong2 d2 = dv[i];
            if ((int)d2.x == NLAST) { int p = atomicAdd(&g_count1, 1); if (p < CAP1) g_s1[p] = (int)srcp[2 * i]; }
            if ((int)d2.y == NLAST) { int p = atomicAdd(&g_count1, 1); if (p < CAP1) g_s1[p] = (int)srcp[2 * i + 1]; }
        }
        for (int e = (nv << 1) + tid; e < E; e += nthreads) {
            if ((int)dstp[e] == NLAST) { int p = atomicAdd(&g_count1, 1); if (p < CAP1) g_s1[p] = (int)srcp[e]; }
        }
    } else {
        const int* __restrict__ srcp = (const int*)eidx;
        const int* __restrict__ dstp = srcp + E;
        int nv = (((unsigned long long)(size_t)dstp & 15ull) == 0ull) ? (E >> 2) : 0;
        const int4* __restrict__ dv = (const int4*)dstp;
        for (int i = tid; i < nv; i += nthreads) {
            int4 d4 = dv[i];
            if (d4.x == NLAST) { int p = atomicAdd(&g_count1, 1); if (p < CAP1) g_s1[p] = srcp[4 * i + 0]; }
            if (d4.y == NLAST) { int p = atomicAdd(&g_count1, 1); if (p < CAP1) g_s1[p] = srcp[4 * i + 1]; }
            if (d4.z == NLAST) { int p = atomicAdd(&g_count1, 1); if (p < CAP1) g_s1[p] = srcp[4 * i + 2]; }
            if (d4.w == NLAST) { int p = atomicAdd(&g_count1, 1); if (p < CAP1) g_s1[p] = srcp[4 * i + 3]; }
        }
        for (int e = (nv << 2) + tid; e < E; e += nthreads) {
            if (dstp[e] == NLAST) { int p = atomicAdd(&g_count1, 1); if (p < CAP1) g_s1[p] = srcp[e]; }
        }
    }
    grid_barrier();

    // ================= P2: mark needed / need_deg ===========================
    if (blockIdx.x == 0) {
        int c1 = g_count1; if (c1 > CAP1) c1 = CAP1;
        for (int k = threadIdx.x; k < c1; k += TPB) {
            int u = g_s1[k];
            g_needed[u] = 1;
            g_need_deg[u] = 1;
        }
        if (threadIdx.x == 0) { g_needed[NLAST] = 1; g_need_deg[NLAST] = 1; }
    }
    grid_barrier();

    // ================= P3: scan — collect edges into needed set ============
    if (mode) {
        const long long* __restrict__ srcp = (const long long*)eidx;
        const long long* __restrict__ dstp = srcp + E;
        int nv = E >> 1;
        const ulonglong2* __restrict__ dv = (const ulonglong2*)dstp;
        for (int i = tid; i < nv; i += nthreads) {
            ulonglong2 d2 = dv[i];
            int d0 = (int)d2.x, d1 = (int)d2.y;
            if (g_needed[d0]) {
                int s = (int)srcp[2 * i];
                int p = atomicAdd(&g_count2, 1);
                if (p < CAP2) { g_pair_src[p] = s; g_pair_dst[p] = d0; }
                g_need_deg[s] = 1;
            }
            if (g_needed[d1]) {
                int s = (int)srcp[2 * i + 1];
                int p = atomicAdd(&g_count2, 1);
                if (p < CAP2) { g_pair_src[p] = s; g_pair_dst[p] = d1; }
                g_need_deg[s] = 1;
            }
        }
        for (int e = (nv << 1) + tid; e < E; e += nthreads) {
            int d = (int)dstp[e];
            if (g_needed[d]) {
                int s = (int)srcp[e];
                int p = atomicAdd(&g_count2, 1);
                if (p < CAP2) { g_pair_src[p] = s; g_pair_dst[p] = d; }
                g_need_deg[s] = 1;
            }
        }
    } else {
        const int* __restrict__ srcp = (const int*)eidx;
        const int* __restrict__ dstp = srcp + E;
        int nv = (((unsigned long long)(size_t)dstp & 15ull) == 0ull) ? (E >> 2) : 0;
        const int4* __restrict__ dv = (const int4*)dstp;
        for (int i = tid; i < nv; i += nthreads) {
            int4 d4 = dv[i];
            #pragma unroll
            for (int j = 0; j < 4; j++) {
                int d = (j == 0) ? d4.x : (j == 1) ? d4.y : (j == 2) ? d4.z : d4.w;
                if (g_needed[d]) {
                    int s = srcp[4 * i + j];
                    int p = atomicAdd(&g_count2, 1);
                    if (p < CAP2) { g_pair_src[p] = s; g_pair_dst[p] = d; }
                    g_need_deg[s] = 1;
                }
            }
        }
        for (int e = (nv << 2) + tid; e < E; e += nthreads) {
            int d = dstp[e];
            if (g_needed[d]) {
                int s = srcp[e];
                int p = atomicAdd(&g_count2, 1);
                if (p < CAP2) { g_pair_src[p] = s; g_pair_dst[p] = d; }
                g_need_deg[s] = 1;
            }
        }
    }
    grid_barrier();

    // ================= P4: filtered degree scan (~1% of edges atomic) ======
    if (mode) {
        const long long* __restrict__ srcp = (const long long*)eidx;
        const long long* __restrict__ dstp = srcp + E;
        int nv = E >> 1;
        const ulonglong2* __restrict__ dv = (const ulonglong2*)dstp;
        for (int i = tid; i < nv; i += nthreads) {
            ulonglong2 d2 = dv[i];
            int d0 = (int)d2.x, d1 = (int)d2.y;
            if (g_need_deg[d0]) atomicAdd(&g_deg[d0], 1);
            if (g_need_deg[d1]) atomicAdd(&g_deg[d1], 1);
        }
        for (int e = (nv << 1) + tid; e < E; e += nthreads) {
            int d = (int)dstp[e];
            if (g_need_deg[d]) atomicAdd(&g_deg[d], 1);
        }
    } else {
        const int* __restrict__ srcp = (const int*)eidx;
        const int* __restrict__ dstp = srcp + E;
        int nv = (((unsigned long long)(size_t)dstp & 15ull) == 0ull) ? (E >> 2) : 0;
        const int4* __restrict__ dv = (const int4*)dstp;
        for (int i = tid; i < nv; i += nthreads) {
            int4 d4 = dv[i];
            if (g_need_deg[d4.x]) atomicAdd(&g_deg[d4.x], 1);
            if (g_need_deg[d4.y]) atomicAdd(&g_deg[d4.y], 1);
            if (g_need_deg[d4.z]) atomicAdd(&g_deg[d4.z], 1);
            if (g_need_deg[d4.w]) atomicAdd(&g_deg[d4.w], 1);
        }
        for (int e = (nv << 2) + tid; e < E; e += nthreads) {
            int d = dstp[e];
            if (g_need_deg[d]) atomicAdd(&g_deg[d], 1);
        }
    }
    grid_barrier();

    // ================= P5: layer-1 aggregation over collected pairs ========
    {
        int c2 = g_count2; if (c2 > CAP2) c2 = CAP2;
        for (int k = tid; k < c2; k += nthreads) {
            int s = g_pair_src[k];
            int d = g_pair_dst[k];
            float dis = rsqrtf((float)(g_deg[s] + 1));
            float did = rsqrtf((float)(g_deg[d] + 1));
            atomicAdd(&g_s[d], x[s] * dis * did);
        }
    }
    grid_barrier();

    // ================= P6: layer-2 @ node N-1 + fc head (1 warp) ===========
    if (blockIdx.x == 0 && threadIdx.x < 32) {
        int lane = threadIdx.x;
        __shared__ float sW1[16], sb1[16], sW2[128], sb2[8], sWfc[8];
        if (lane < 16) { sW1[lane] = W1[lane]; sb1[lane] = b1[lane]; }
        if (lane < 8)  { sb2[lane] = b2[lane]; sWfc[lane] = Wfc[lane]; }
        for (int k = lane; k < 128; k += 32) sW2[k] = W2[k];
        __syncwarp();

        const float dinvL = rsqrtf((float)(g_deg[NLAST] + 1));
        int c1 = g_count1; if (c1 > CAP1) c1 = CAP1;

        float agg[8];
        #pragma unroll
        for (int j = 0; j < 8; j++) agg[j] = 0.0f;

        // k in [0, c1): real edges into N-1; k == c1: appended self-loop.
        for (int k = lane; k <= c1; k += 32) {
            int u = (k == c1) ? NLAST : g_s1[k];
            float du = rsqrtf((float)(g_deg[u] + 1));
            float norm = du * dinvL;
            float su = g_s[u] + x[u] * du * du;   // layer-1 agg incl. self-loop
            float h1[16];
            #pragma unroll
            for (int j = 0; j < 16; j++)
                h1[j] = fmaxf(fmaf(su, sW1[j], sb1[j]), 0.0f);
            #pragma unroll
            for (int j = 0; j < 8; j++) {
                float v = 0.0f;
                #pragma unroll
                for (int t = 0; t < 16; t++) v = fmaf(h1[t], sW2[t * 8 + j], v);
                agg[j] = fmaf(v, norm, agg[j]);
            }
        }
        #pragma unroll
        for (int off = 16; off > 0; off >>= 1) {
            #pragma unroll
            for (int j = 0; j < 8; j++)
                agg[j] += __shfl_down_sync(0xffffffff, agg[j], off);
        }
        if (lane == 0) {
            float o = bfc[0];
            #pragma unroll
            for (int j = 0; j < 8; j++) {
                float h2 = fmaxf(agg[j] + sb2[j], 0.0f);
                o = fmaf(h2, sWfc[j], o);
            }
            out[0] = o;
        }
    }
}

// ---------------------------------------------------------------------------
extern "C" void kernel_launch(void* const* d_in, const int* in_sizes, int n_in,
                              void* d_out, int out_size) {
    const float* x    = (const float*)d_in[0];
    const void*  eidx = d_in[1];
    const float* W1   = (const float*)d_in[2];
    const float* b1   = (const float*)d_in[3];
    const float* W2   = (const float*)d_in[4];
    const float* b2   = (const float*)d_in[5];
    const float* Wfc  = (const float*)d_in[6];
    const float* bfc  = (const float*)d_in[7];
    float* out = (float*)d_out;

    int E = in_sizes[1] / 2;

    gcn_fused_kernel<<<GRID, TPB>>>(eidx, x, W1, b1, W2, b2, Wfc, bfc, out, E);
}

// round 5
// speedup vs baseline: 1.5626x; 1.1152x over previous
#include <cuda_runtime.h>
#include <cuda_bf16.h>
#include <cstdint>
#include <cstddef>

#define NNODES 100000
#define NLAST  (NNODES - 1)
#define NWORDS 3125            // ceil(100000/32)
#define CAP1   4096
#define CAP2   32768
#define GRID   148
#define TPB    1024

// ---- scratch (device globals; no allocation allowed) ----------------------
__device__ int           g_deg[NNODES];
__device__ float         g_s[NNODES];
__device__ unsigned int  g_needed_bm[NWORDS];    // layer-1 dsts to aggregate
__device__ unsigned int  g_need_deg_bm[NWORDS];  // nodes whose degree matters
__device__ int           g_s1[CAP1];             // srcs of edges into N-1
__device__ int           g_pair_src[CAP2];       // edges into needed set
__device__ int           g_pair_dst[CAP2];
__device__ int           g_count1;
__device__ int           g_count2;
__device__ int           g_mode64;
__device__ unsigned int           g_bar_count;
__device__ volatile unsigned int  g_bar_gen;

// ---- software grid barrier (GRID blocks, 1/SM, co-resident) ---------------
__device__ __forceinline__ void grid_barrier() {
    __syncthreads();
    if (threadIdx.x == 0) {
        __threadfence();
        unsigned gen = g_bar_gen;
        unsigned arrived = atomicAdd(&g_bar_count, 1u);
        if (arrived == GRID - 1) {
            g_bar_count = 0u;
            __threadfence();
            g_bar_gen = gen + 1u;
        } else {
            while (g_bar_gen == gen) { }
        }
        __threadfence();
    }
    __syncthreads();
}

// ---------------------------------------------------------------------------
__global__ void __launch_bounds__(TPB, 1)
gcn_fused_kernel(const void* __restrict__ eidx,
                 const float* __restrict__ x,
                 const float* __restrict__ W1, const float* __restrict__ b1,
                 const float* __restrict__ W2, const float* __restrict__ b2,
                 const float* __restrict__ Wfc, const float* __restrict__ bfc,
                 float* __restrict__ out, int E) {
    const int tid      = blockIdx.x * TPB + threadIdx.x;
    const int nthreads = GRID * TPB;

    __shared__ unsigned int s_bm[NWORDS];   // 12.5 KB membership bitmask

    // ================= P0: zero scratch + dtype detect ======================
    for (int n = tid; n < NNODES; n += nthreads) {
        g_deg[n] = 0;
        g_s[n] = 0.0f;
    }
    for (int wdx = tid; wdx < NWORDS; wdx += nthreads) {
        g_needed_bm[wdx] = 0u;
        g_need_deg_bm[wdx] = 0u;
    }
    if (tid == 0) {
        g_count1 = 0;
        g_count2 = 0;
        // int64 little-endian: odd 32-bit words of values < 2^31 are all 0.
        const unsigned int* w = (const unsigned int*)eidx;
        int all0 = 1;
        #pragma unroll
        for (int i = 0; i < 32; i++)
            if (w[2 * i + 1] != 0u) all0 = 0;
        g_mode64 = all0;
    }
    grid_barrier();

    const int mode = g_mode64;

    // ================= P1: scan — edges with dst == N-1 ====================
    if (mode) {
        const long long* __restrict__ srcp = (const long long*)eidx;
        const long long* __restrict__ dstp = srcp + E;
        int nv = E >> 1;
        const ulonglong2* __restrict__ dv = (const ulonglong2*)dstp;
        for (int i = tid; i < nv; i += nthreads) {
            ulonglong2 d2 = dv[i];
            if ((int)d2.x == NLAST) { int p = atomicAdd(&g_count1, 1); if (p < CAP1) g_s1[p] = (int)srcp[2 * i]; }
            if ((int)d2.y == NLAST) { int p = atomicAdd(&g_count1, 1); if (p < CAP1) g_s1[p] = (int)srcp[2 * i + 1]; }
        }
        for (int e = (nv << 1) + tid; e < E; e += nthreads) {
            if ((int)dstp[e] == NLAST) { int p = atomicAdd(&g_count1, 1); if (p < CAP1) g_s1[p] = (int)srcp[e]; }
        }
    } else {
        const int* __restrict__ srcp = (const int*)eidx;
        const int* __restrict__ dstp = srcp + E;
        int nv = (((unsigned long long)(size_t)dstp & 15ull) == 0ull) ? (E >> 2) : 0;
        const int4* __restrict__ dv = (const int4*)dstp;
        for (int i = tid; i < nv; i += nthreads) {
            int4 d4 = dv[i];
            if (d4.x == NLAST) { int p = atomicAdd(&g_count1, 1); if (p < CAP1) g_s1[p] = srcp[4 * i + 0]; }
            if (d4.y == NLAST) { int p = atomicAdd(&g_count1, 1); if (p < CAP1) g_s1[p] = srcp[4 * i + 1]; }
            if (d4.z == NLAST) { int p = atomicAdd(&g_count1, 1); if (p < CAP1) g_s1[p] = srcp[4 * i + 2]; }
            if (d4.w == NLAST) { int p = atomicAdd(&g_count1, 1); if (p < CAP1) g_s1[p] = srcp[4 * i + 3]; }
        }
        for (int e = (nv << 2) + tid; e < E; e += nthreads) {
            if (dstp[e] == NLAST) { int p = atomicAdd(&g_count1, 1); if (p < CAP1) g_s1[p] = srcp[e]; }
        }
    }
    grid_barrier();

    // ================= P2: build needed bitmask (global) ====================
    if (blockIdx.x == 0) {
        int c1 = g_count1; if (c1 > CAP1) c1 = CAP1;
        for (int k = threadIdx.x; k < c1; k += TPB) {
            int u = g_s1[k];
            atomicOr(&g_needed_bm[u >> 5], 1u << (u & 31));
            atomicOr(&g_need_deg_bm[u >> 5], 1u << (u & 31));
        }
        if (threadIdx.x == 0) {
            atomicOr(&g_needed_bm[NLAST >> 5], 1u << (NLAST & 31));
            atomicOr(&g_need_deg_bm[NLAST >> 5], 1u << (NLAST & 31));
        }
    }
    grid_barrier();

    // copy needed bitmask into shared memory
    for (int wdx = threadIdx.x; wdx < NWORDS; wdx += TPB)
        s_bm[wdx] = g_needed_bm[wdx];
    __syncthreads();

    // ================= P3: scan — edges into needed set (smem bm test) =====
    if (mode) {
        const long long* __restrict__ srcp = (const long long*)eidx;
        const long long* __restrict__ dstp = srcp + E;
        int nv = E >> 1;
        const ulonglong2* __restrict__ dv = (const ulonglong2*)dstp;
        for (int i = tid; i < nv; i += nthreads) {
            ulonglong2 d2 = dv[i];
            int d0 = (int)d2.x, d1 = (int)d2.y;
            if ((s_bm[d0 >> 5] >> (d0 & 31)) & 1u) {
                int s = (int)srcp[2 * i];
                int p = atomicAdd(&g_count2, 1);
                if (p < CAP2) { g_pair_src[p] = s; g_pair_dst[p] = d0; }
                atomicOr(&g_need_deg_bm[s >> 5], 1u << (s & 31));
            }
            if ((s_bm[d1 >> 5] >> (d1 & 31)) & 1u) {
                int s = (int)srcp[2 * i + 1];
                int p = atomicAdd(&g_count2, 1);
                if (p < CAP2) { g_pair_src[p] = s; g_pair_dst[p] = d1; }
                atomicOr(&g_need_deg_bm[s >> 5], 1u << (s & 31));
            }
        }
        for (int e = (nv << 1) + tid; e < E; e += nthreads) {
            int d = (int)dstp[e];
            if ((s_bm[d >> 5] >> (d & 31)) & 1u) {
                int s = (int)srcp[e];
                int p = atomicAdd(&g_count2, 1);
                if (p < CAP2) { g_pair_src[p] = s; g_pair_dst[p] = d; }
                atomicOr(&g_need_deg_bm[s >> 5], 1u << (s & 31));
            }
        }
    } else {
        const int* __restrict__ srcp = (const int*)eidx;
        const int* __restrict__ dstp = srcp + E;
        int nv = (((unsigned long long)(size_t)dstp & 15ull) == 0ull) ? (E >> 2) : 0;
        const int4* __restrict__ dv = (const int4*)dstp;
        for (int i = tid; i < nv; i += nthreads) {
            int4 d4 = dv[i];
            #pragma unroll
            for (int j = 0; j < 4; j++) {
                int d = (j == 0) ? d4.x : (j == 1) ? d4.y : (j == 2) ? d4.z : d4.w;
                if ((s_bm[d >> 5] >> (d & 31)) & 1u) {
                    int s = srcp[4 * i + j];
                    int p = atomicAdd(&g_count2, 1);
                    if (p < CAP2) { g_pair_src[p] = s; g_pair_dst[p] = d; }
                    atomicOr(&g_need_deg_bm[s >> 5], 1u << (s & 31));
                }
            }
        }
        for (int e = (nv << 2) + tid; e < E; e += nthreads) {
            int d = dstp[e];
            if ((s_bm[d >> 5] >> (d & 31)) & 1u) {
                int s = srcp[e];
                int p = atomicAdd(&g_count2, 1);
                if (p < CAP2) { g_pair_src[p] = s; g_pair_dst[p] = d; }
                atomicOr(&g_need_deg_bm[s >> 5], 1u << (s & 31));
            }
        }
    }
    grid_barrier();

    // copy need_deg bitmask into shared memory (reuse s_bm)
    for (int wdx = threadIdx.x; wdx < NWORDS; wdx += TPB)
        s_bm[wdx] = g_need_deg_bm[wdx];
    __syncthreads();

    // ================= P4: filtered degree scan (smem bm test) =============
    if (mode) {
        const long long* __restrict__ srcp = (const long long*)eidx;
        const long long* __restrict__ dstp = srcp + E;
        int nv = E >> 1;
        const ulonglong2* __restrict__ dv = (const ulonglong2*)dstp;
        for (int i = tid; i < nv; i += nthreads) {
            ulonglong2 d2 = dv[i];
            int d0 = (int)d2.x, d1 = (int)d2.y;
            if ((s_bm[d0 >> 5] >> (d0 & 31)) & 1u) atomicAdd(&g_deg[d0], 1);
            if ((s_bm[d1 >> 5] >> (d1 & 31)) & 1u) atomicAdd(&g_deg[d1], 1);
        }
        for (int e = (nv << 1) + tid; e < E; e += nthreads) {
            int d = (int)dstp[e];
            if ((s_bm[d >> 5] >> (d & 31)) & 1u) atomicAdd(&g_deg[d], 1);
        }
    } else {
        const int* __restrict__ srcp = (const int*)eidx;
        const int* __restrict__ dstp = srcp + E;
        int nv = (((unsigned long long)(size_t)dstp & 15ull) == 0ull) ? (E >> 2) : 0;
        const int4* __restrict__ dv = (const int4*)dstp;
        for (int i = tid; i < nv; i += nthreads) {
            int4 d4 = dv[i];
            if ((s_bm[d4.x >> 5] >> (d4.x & 31)) & 1u) atomicAdd(&g_deg[d4.x], 1);
            if ((s_bm[d4.y >> 5] >> (d4.y & 31)) & 1u) atomicAdd(&g_deg[d4.y], 1);
            if ((s_bm[d4.z >> 5] >> (d4.z & 31)) & 1u) atomicAdd(&g_deg[d4.z], 1);
            if ((s_bm[d4.w >> 5] >> (d4.w & 31)) & 1u) atomicAdd(&g_deg[d4.w], 1);
        }
        for (int e = (nv << 2) + tid; e < E; e += nthreads) {
            int d = dstp[e];
            if ((s_bm[d >> 5] >> (d & 31)) & 1u) atomicAdd(&g_deg[d], 1);
        }
    }
    grid_barrier();

    // ================= P5: layer-1 aggregation over pairs ==================
    {
        int c2 = g_count2; if (c2 > CAP2) c2 = CAP2;
        for (int k = tid; k < c2; k += nthreads) {
            int s = g_pair_src[k];
            int d = g_pair_dst[k];
            float dis = rsqrtf((float)(g_deg[s] + 1));
            float did = rsqrtf((float)(g_deg[d] + 1));
            atomicAdd(&g_s[d], x[s] * dis * did);
        }
    }
    grid_barrier();

    // ================= P6: layer-2 @ node N-1 + fc head (1 warp) ===========
    if (blockIdx.x == 0 && threadIdx.x < 32) {
        int lane = threadIdx.x;
        __shared__ float sW1[16], sb1[16], sW2[128], sb2[8], sWfc[8];
        if (lane < 16) { sW1[lane] = W1[lane]; sb1[lane] = b1[lane]; }
        if (lane < 8)  { sb2[lane] = b2[lane]; sWfc[lane] = Wfc[lane]; }
        for (int k = lane; k < 128; k += 32) sW2[k] = W2[k];
        __syncwarp();

        const float dinvL = rsqrtf((float)(g_deg[NLAST] + 1));
        int c1 = g_count1; if (c1 > CAP1) c1 = CAP1;

        float agg[8];
        #pragma unroll
        for (int j = 0; j < 8; j++) agg[j] = 0.0f;

        // k in [0, c1): real edges into N-1; k == c1: appended self-loop.
        for (int k = lane; k <= c1; k += 32) {
            int u = (k == c1) ? NLAST : g_s1[k];
            float du = rsqrtf((float)(g_deg[u] + 1));
            float norm = du * dinvL;
            float su = g_s[u] + x[u] * du * du;   // layer-1 agg incl. self-loop
            float h1[16];
            #pragma unroll
            for (int j = 0; j < 16; j++)
                h1[j] = fmaxf(fmaf(su, sW1[j], sb1[j]), 0.0f);
            #pragma unroll
            for (int j = 0; j < 8; j++) {
                float v = 0.0f;
                #pragma unroll
                for (int t = 0; t < 16; t++) v = fmaf(h1[t], sW2[t * 8 + j], v);
                agg[j] = fmaf(v, norm, agg[j]);
            }
        }
        #pragma unroll
        for (int off = 16; off > 0; off >>= 1) {
            #pragma unroll
            for (int j = 0; j < 8; j++)
                agg[j] += __shfl_down_sync(0xffffffff, agg[j], off);
        }
        if (lane == 0) {
            float o = bfc[0];
            #pragma unroll
            for (int j = 0; j < 8; j++) {
                float h2 = fmaxf(agg[j] + sb2[j], 0.0f);
                o = fmaf(h2, sWfc[j], o);
            }
            out[0] = o;
        }
    }
}

// ---------------------------------------------------------------------------
extern "C" void kernel_launch(void* const* d_in, const int* in_sizes, int n_in,
                              void* d_out, int out_size) {
    const float* x    = (const float*)d_in[0];
    const void*  eidx = d_in[1];
    const float* W1   = (const float*)d_in[2];
    const float* b1   = (const float*)d_in[3];
    const float* W2   = (const float*)d_in[4];
    const float* b2   = (const float*)d_in[5];
    const float* Wfc  = (const float*)d_in[6];
    const float* bfc  = (const float*)d_in[7];
    float* out = (float*)d_out;

    int E = in_sizes[1] / 2;

    gcn_fused_kernel<<<GRID, TPB>>>(eidx, x, W1, b1, W2, b2, Wfc, bfc, out, E);
}

// round 6
// speedup vs baseline: 1.8046x; 1.1549x over previous
#include <cuda_runtime.h>
#include <cuda_bf16.h>
#include <cstdint>
#include <cstddef>

#define NNODES 100000
#define NLAST  (NNODES - 1)
#define NWORDS 3125            // ceil(100000/32)
#define CAP1   4096
#define CAP2   32768
#define GRID   148
#define TPB    1024

// ---- scratch (device globals; no allocation allowed) ----------------------
__device__ int           g_deg[NNODES];
__device__ float         g_s[NNODES];
__device__ int           g_s1[CAP1];             // srcs of edges into N-1
__device__ int           g_pair_src[CAP2];       // edges into needed set
__device__ int           g_pair_dst[CAP2];
__device__ int           g_count1;
__device__ int           g_count2;
__device__ int           g_mode64;
__device__ unsigned int           g_bar_count;
__device__ volatile unsigned int  g_bar_gen;

// ---- software grid barrier (GRID blocks, 1/SM, co-resident) ---------------
__device__ __forceinline__ void grid_barrier() {
    __syncthreads();
    if (threadIdx.x == 0) {
        __threadfence();
        unsigned gen = g_bar_gen;
        unsigned arrived = atomicAdd(&g_bar_count, 1u);
        if (arrived == GRID - 1) {
            g_bar_count = 0u;
            __threadfence();
            g_bar_gen = gen + 1u;
        } else {
            while (g_bar_gen == gen) { }
        }
        __threadfence();
    }
    __syncthreads();
}

// membership test in shared bitmask
#define BM_TEST(bm, v)  (((bm)[(v) >> 5] >> ((v) & 31)) & 1u)

// ---------------------------------------------------------------------------
__global__ void __launch_bounds__(TPB, 1)
gcn_fused_kernel(const void* __restrict__ eidx,
                 const float* __restrict__ x,
                 const float* __restrict__ W1, const float* __restrict__ b1,
                 const float* __restrict__ W2, const float* __restrict__ b2,
                 const float* __restrict__ Wfc, const float* __restrict__ bfc,
                 float* __restrict__ out, int E) {
    const int tid      = blockIdx.x * TPB + threadIdx.x;
    const int nthreads = GRID * TPB;

    __shared__ unsigned int s_bm[NWORDS];   // 12.5 KB membership bitmask

    // ================= P0: zero scratch + dtype detect ======================
    for (int n = tid; n < NNODES; n += nthreads) {
        g_deg[n] = 0;
        g_s[n] = 0.0f;
    }
    if (tid == 0) {
        g_count1 = 0;
        g_count2 = 0;
        // int64 little-endian: odd 32-bit words of values < 2^31 are all 0.
        const unsigned int* w = (const unsigned int*)eidx;
        int all0 = 1;
        #pragma unroll
        for (int i = 0; i < 32; i++)
            if (w[2 * i + 1] != 0u) all0 = 0;
        g_mode64 = all0;
    }
    grid_barrier();

    const int mode = g_mode64;

    // ================= P1: scan — edges with dst == N-1 (MLP=4) ============
    if (mode) {
        const long long* __restrict__ srcp = (const long long*)eidx;
        const long long* __restrict__ dstp = srcp + E;
        const int nv = E >> 1;
        const ulonglong2* __restrict__ dv = (const ulonglong2*)dstp;
        const int step = nthreads;
        int i = tid;
        #define P1TEST2(d2, base)                                                              \
            do {                                                                               \
                if ((int)(d2).x == NLAST) { int p = atomicAdd(&g_count1, 1); if (p < CAP1) g_s1[p] = (int)srcp[2*(base)]; }     \
                if ((int)(d2).y == NLAST) { int p = atomicAdd(&g_count1, 1); if (p < CAP1) g_s1[p] = (int)srcp[2*(base)+1]; }   \
            } while (0)
        for (; i + 3 * step < nv; i += 4 * step) {
            ulonglong2 a = dv[i], b = dv[i + step], c = dv[i + 2 * step], d = dv[i + 3 * step];
            P1TEST2(a, i); P1TEST2(b, i + step); P1TEST2(c, i + 2 * step); P1TEST2(d, i + 3 * step);
        }
        for (; i < nv; i += step) { ulonglong2 a = dv[i]; P1TEST2(a, i); }
        for (int e = (nv << 1) + tid; e < E; e += step) {
            if ((int)dstp[e] == NLAST) { int p = atomicAdd(&g_count1, 1); if (p < CAP1) g_s1[p] = (int)srcp[e]; }
        }
        #undef P1TEST2
    } else {
        const int* __restrict__ srcp = (const int*)eidx;
        const int* __restrict__ dstp = srcp + E;
        const int nv = (((unsigned long long)(size_t)dstp & 15ull) == 0ull) ? (E >> 2) : 0;
        const int4* __restrict__ dv = (const int4*)dstp;
        const int step = nthreads;
        int i = tid;
        #define P1TEST4(d4, base)                                                              \
            do {                                                                               \
                if ((d4).x == NLAST) { int p = atomicAdd(&g_count1, 1); if (p < CAP1) g_s1[p] = srcp[4*(base)+0]; }  \
                if ((d4).y == NLAST) { int p = atomicAdd(&g_count1, 1); if (p < CAP1) g_s1[p] = srcp[4*(base)+1]; }  \
                if ((d4).z == NLAST) { int p = atomicAdd(&g_count1, 1); if (p < CAP1) g_s1[p] = srcp[4*(base)+2]; }  \
                if ((d4).w == NLAST) { int p = atomicAdd(&g_count1, 1); if (p < CAP1) g_s1[p] = srcp[4*(base)+3]; }  \
            } while (0)
        for (; i + 3 * step < nv; i += 4 * step) {
            int4 a = dv[i], b = dv[i + step], c = dv[i + 2 * step], d = dv[i + 3 * step];
            P1TEST4(a, i); P1TEST4(b, i + step); P1TEST4(c, i + 2 * step); P1TEST4(d, i + 3 * step);
        }
        for (; i < nv; i += step) { int4 a = dv[i]; P1TEST4(a, i); }
        for (int e = (nv << 2) + tid; e < E; e += step) {
            if (dstp[e] == NLAST) { int p = atomicAdd(&g_count1, 1); if (p < CAP1) g_s1[p] = srcp[e]; }
        }
        #undef P1TEST4
    }
    grid_barrier();

    // build needed bitmask per-block in smem from g_s1 (~33 entries)
    for (int wdx = threadIdx.x; wdx < NWORDS; wdx += TPB) s_bm[wdx] = 0u;
    __syncthreads();
    {
        int c1 = g_count1; if (c1 > CAP1) c1 = CAP1;
        for (int k = threadIdx.x; k < c1; k += TPB) {
            int u = g_s1[k];
            atomicOr(&s_bm[u >> 5], 1u << (u & 31));
        }
        if (threadIdx.x == 0) atomicOr(&s_bm[NLAST >> 5], 1u << (NLAST & 31));
    }
    __syncthreads();

    // ================= P3: scan — edges into needed set (MLP=4) ============
    if (mode) {
        const long long* __restrict__ srcp = (const long long*)eidx;
        const long long* __restrict__ dstp = srcp + E;
        const int nv = E >> 1;
        const ulonglong2* __restrict__ dv = (const ulonglong2*)dstp;
        const int step = nthreads;
        int i = tid;
        #define P3TEST2(d2, base)                                                              \
            do {                                                                               \
                int d0 = (int)(d2).x, d1 = (int)(d2).y;                                        \
                if (BM_TEST(s_bm, d0)) { int s = (int)srcp[2*(base)];   int p = atomicAdd(&g_count2, 1); if (p < CAP2) { g_pair_src[p] = s; g_pair_dst[p] = d0; } } \
                if (BM_TEST(s_bm, d1)) { int s = (int)srcp[2*(base)+1]; int p = atomicAdd(&g_count2, 1); if (p < CAP2) { g_pair_src[p] = s; g_pair_dst[p] = d1; } } \
            } while (0)
        for (; i + 3 * step < nv; i += 4 * step) {
            ulonglong2 a = dv[i], b = dv[i + step], c = dv[i + 2 * step], d = dv[i + 3 * step];
            P3TEST2(a, i); P3TEST2(b, i + step); P3TEST2(c, i + 2 * step); P3TEST2(d, i + 3 * step);
        }
        for (; i < nv; i += step) { ulonglong2 a = dv[i]; P3TEST2(a, i); }
        for (int e = (nv << 1) + tid; e < E; e += step) {
            int d = (int)dstp[e];
            if (BM_TEST(s_bm, d)) { int s = (int)srcp[e]; int p = atomicAdd(&g_count2, 1); if (p < CAP2) { g_pair_src[p] = s; g_pair_dst[p] = d; } }
        }
        #undef P3TEST2
    } else {
        const int* __restrict__ srcp = (const int*)eidx;
        const int* __restrict__ dstp = srcp + E;
        const int nv = (((unsigned long long)(size_t)dstp & 15ull) == 0ull) ? (E >> 2) : 0;
        const int4* __restrict__ dv = (const int4*)dstp;
        const int step = nthreads;
        int i = tid;
        #define P3TEST4(d4, base)                                                              \
            do {                                                                               \
                if (BM_TEST(s_bm, (d4).x)) { int s = srcp[4*(base)+0]; int p = atomicAdd(&g_count2, 1); if (p < CAP2) { g_pair_src[p] = s; g_pair_dst[p] = (d4).x; } } \
                if (BM_TEST(s_bm, (d4).y)) { int s = srcp[4*(base)+1]; int p = atomicAdd(&g_count2, 1); if (p < CAP2) { g_pair_src[p] = s; g_pair_dst[p] = (d4).y; } } \
                if (BM_TEST(s_bm, (d4).z)) { int s = srcp[4*(base)+2]; int p = atomicAdd(&g_count2, 1); if (p < CAP2) { g_pair_src[p] = s; g_pair_dst[p] = (d4).z; } } \
                if (BM_TEST(s_bm, (d4).w)) { int s = srcp[4*(base)+3]; int p = atomicAdd(&g_count2, 1); if (p < CAP2) { g_pair_src[p] = s; g_pair_dst[p] = (d4).w; } } \
            } while (0)
        for (; i + 3 * step < nv; i += 4 * step) {
            int4 a = dv[i], b = dv[i + step], c = dv[i + 2 * step], d = dv[i + 3 * step];
            P3TEST4(a, i); P3TEST4(b, i + step); P3TEST4(c, i + 2 * step); P3TEST4(d, i + 3 * step);
        }
        for (; i < nv; i += step) { int4 a = dv[i]; P3TEST4(a, i); }
        for (int e = (nv << 2) + tid; e < E; e += step) {
            int d = dstp[e];
            if (BM_TEST(s_bm, d)) { int s = srcp[e]; int p = atomicAdd(&g_count2, 1); if (p < CAP2) { g_pair_src[p] = s; g_pair_dst[p] = d; } }
        }
        #undef P3TEST4
    }
    grid_barrier();

    // build need_deg bitmask per-block: needed set ∪ pair srcs
    {
        int c1 = g_count1; if (c1 > CAP1) c1 = CAP1;   // already in s_bm
        int c2 = g_count2; if (c2 > CAP2) c2 = CAP2;
        (void)c1;
        for (int k = threadIdx.x; k < c2; k += TPB) {
            int u = g_pair_src[k];
            atomicOr(&s_bm[u >> 5], 1u << (u & 31));
        }
    }
    __syncthreads();

    // ================= P4: filtered degree scan (MLP=4) ====================
    if (mode) {
        const long long* __restrict__ dstp = (const long long*)eidx + E;
        const int nv = E >> 1;
        const ulonglong2* __restrict__ dv = (const ulonglong2*)dstp;
        const int step = nthreads;
        int i = tid;
        #define P4TEST2(d2)                                                                    \
            do {                                                                               \
                int d0 = (int)(d2).x, d1 = (int)(d2).y;                                        \
                if (BM_TEST(s_bm, d0)) atomicAdd(&g_deg[d0], 1);                               \
                if (BM_TEST(s_bm, d1)) atomicAdd(&g_deg[d1], 1);                               \
            } while (0)
        for (; i + 3 * step < nv; i += 4 * step) {
            ulonglong2 a = dv[i], b = dv[i + step], c = dv[i + 2 * step], d = dv[i + 3 * step];
            P4TEST2(a); P4TEST2(b); P4TEST2(c); P4TEST2(d);
        }
        for (; i < nv; i += step) { ulonglong2 a = dv[i]; P4TEST2(a); }
        for (int e = (nv << 1) + tid; e < E; e += step) {
            int d = (int)dstp[e];
            if (BM_TEST(s_bm, d)) atomicAdd(&g_deg[d], 1);
        }
        #undef P4TEST2
    } else {
        const int* __restrict__ dstp = (const int*)eidx + E;
        const int nv = (((unsigned long long)(size_t)dstp & 15ull) == 0ull) ? (E >> 2) : 0;
        const int4* __restrict__ dv = (const int4*)dstp;
        const int step = nthreads;
        int i = tid;
        #define P4TEST4(d4)                                                                    \
            do {                                                                               \
                if (BM_TEST(s_bm, (d4).x)) atomicAdd(&g_deg[(d4).x], 1);                       \
                if (BM_TEST(s_bm, (d4).y)) atomicAdd(&g_deg[(d4).y], 1);                       \
                if (BM_TEST(s_bm, (d4).z)) atomicAdd(&g_deg[(d4).z], 1);                       \
                if (BM_TEST(s_bm, (d4).w)) atomicAdd(&g_deg[(d4).w], 1);                       \
            } while (0)
        for (; i + 3 * step < nv; i += 4 * step) {
            int4 a = dv[i], b = dv[i + step], c = dv[i + 2 * step], d = dv[i + 3 * step];
            P4TEST4(a); P4TEST4(b); P4TEST4(c); P4TEST4(d);
        }
        for (; i < nv; i += step) { int4 a = dv[i]; P4TEST4(a); }
        for (int e = (nv << 2) + tid; e < E; e += step) {
            int d = dstp[e];
            if (BM_TEST(s_bm, d)) atomicAdd(&g_deg[d], 1);
        }
        #undef P4TEST4
    }
    grid_barrier();

    // ================= P5: layer-1 aggregation over pairs ==================
    {
        int c2 = g_count2; if (c2 > CAP2) c2 = CAP2;
        for (int k = tid; k < c2; k += nthreads) {
            int s = g_pair_src[k];
            int d = g_pair_dst[k];
            float dis = rsqrtf((float)(g_deg[s] + 1));
            float did = rsqrtf((float)(g_deg[d] + 1));
            atomicAdd(&g_s[d], x[s] * dis * did);
        }
    }
    grid_barrier();

    // ================= P6: layer-2 @ node N-1 + fc head (1 warp) ===========
    if (blockIdx.x == 0 && threadIdx.x < 32) {
        int lane = threadIdx.x;
        __shared__ float sW1[16], sb1[16], sW2[128], sb2[8], sWfc[8];
        if (lane < 16) { sW1[lane] = W1[lane]; sb1[lane] = b1[lane]; }
        if (lane < 8)  { sb2[lane] = b2[lane]; sWfc[lane] = Wfc[lane]; }
        for (int k = lane; k < 128; k += 32) sW2[k] = W2[k];
        __syncwarp();

        const float dinvL = rsqrtf((float)(g_deg[NLAST] + 1));
        int c1 = g_count1; if (c1 > CAP1) c1 = CAP1;

        float agg[8];
        #pragma unroll
        for (int j = 0; j < 8; j++) agg[j] = 0.0f;

        // k in [0, c1): real edges into N-1; k == c1: appended self-loop.
        for (int k = lane; k <= c1; k += 32) {
            int u = (k == c1) ? NLAST : g_s1[k];
            float du = rsqrtf((float)(g_deg[u] + 1));
            float norm = du * dinvL;
            float su = g_s[u] + x[u] * du * du;   // layer-1 agg incl. self-loop
            float h1[16];
            #pragma unroll
            for (int j = 0; j < 16; j++)
                h1[j] = fmaxf(fmaf(su, sW1[j], sb1[j]), 0.0f);
            #pragma unroll
            for (int j = 0; j < 8; j++) {
                float v = 0.0f;
                #pragma unroll
                for (int t = 0; t < 16; t++) v = fmaf(h1[t], sW2[t * 8 + j], v);
                agg[j] = fmaf(v, norm, agg[j]);
            }
        }
        #pragma unroll
        for (int off = 16; off > 0; off >>= 1) {
            #pragma unroll
            for (int j = 0; j < 8; j++)
                agg[j] += __shfl_down_sync(0xffffffff, agg[j], off);
        }
        if (lane == 0) {
            float o = bfc[0];
            #pragma unroll
            for (int j = 0; j < 8; j++) {
                float h2 = fmaxf(agg[j] + sb2[j], 0.0f);
                o = fmaf(h2, sWfc[j], o);
            }
            out[0] = o;
        }
    }
}

// ---------------------------------------------------------------------------
extern "C" void kernel_launch(void* const* d_in, const int* in_sizes, int n_in,
                              void* d_out, int out_size) {
    const float* x    = (const float*)d_in[0];
    const void*  eidx = d_in[1];
    const float* W1   = (const float*)d_in[2];
    const float* b1   = (const float*)d_in[3];
    const float* W2   = (const float*)d_in[4];
    const float* b2   = (const float*)d_in[5];
    const float* Wfc  = (const float*)d_in[6];
    const float* bfc  = (const float*)d_in[7];
    float* out = (float*)d_out;

    int E = in_sizes[1] / 2;

    gcn_fused_kernel<<<GRID, TPB>>>(eidx, x, W1, b1, W2, b2, Wfc, bfc, out, E);
}

// round 7
// speedup vs baseline: 1.8870x; 1.0457x over previous
#include <cuda_runtime.h>
#include <cuda_bf16.h>
#include <cstdint>
#include <cstddef>

#define NNODES 100000
#define NLAST  (NNODES - 1)
#define NWORDS 3125            // ceil(100000/32)
#define CAP1   4096
#define CAP2   32768
#define GRID   148
#define TPB    1024

// ---- scratch (device globals; zero at module load; cleaned at kernel end) --
__device__ int           g_deg[NNODES];        // only ~2k entries ever touched
__device__ float         g_s[NNODES];          // only ~33 entries ever touched
__device__ int           g_s1[CAP1];           // srcs of edges into N-1
__device__ int           g_pair_src[CAP2];     // edges into needed set
__device__ int           g_pair_dst[CAP2];
__device__ int           g_count1;
__device__ int           g_count2;
__device__ unsigned int           g_bar_count;
__device__ volatile unsigned int  g_bar_gen;

// ---- software grid barrier (GRID blocks, 1/SM, co-resident) ---------------
__device__ __forceinline__ void grid_barrier() {
    __syncthreads();
    if (threadIdx.x == 0) {
        __threadfence();
        unsigned gen = g_bar_gen;
        unsigned arrived = atomicAdd(&g_bar_count, 1u);
        if (arrived == GRID - 1) {
            g_bar_count = 0u;
            __threadfence();
            g_bar_gen = gen + 1u;
        } else {
            while (g_bar_gen == gen) { }
        }
        __threadfence();
    }
    __syncthreads();
}

#define BM_TEST(bm, v)  (((bm)[(v) >> 5] >> ((v) & 31)) & 1u)

// ---------------------------------------------------------------------------
__global__ void __launch_bounds__(TPB, 1)
gcn_fused_kernel(const void* __restrict__ eidx,
                 const float* __restrict__ x,
                 const float* __restrict__ W1, const float* __restrict__ b1,
                 const float* __restrict__ W2, const float* __restrict__ b2,
                 const float* __restrict__ Wfc, const float* __restrict__ bfc,
                 float* __restrict__ out, int E) {
    const int tid      = blockIdx.x * TPB + threadIdx.x;
    const int nthreads = GRID * TPB;

    __shared__ unsigned int s_bm[NWORDS];   // 12.5 KB membership bitmask
    __shared__ int sh_mode;

    // per-block dtype detect (all blocks read the same 256B; L2-broadcast)
    if (threadIdx.x == 0) {
        const unsigned int* w = (const unsigned int*)eidx;
        int all0 = 1;
        #pragma unroll
        for (int i = 0; i < 32; i++)
            if (w[2 * i + 1] != 0u) all0 = 0;
        sh_mode = all0;
    }
    // zero smem bitmask concurrently
    for (int wdx = threadIdx.x; wdx < NWORDS; wdx += TPB) s_bm[wdx] = 0u;
    __syncthreads();
    const int mode = sh_mode;

    // ================= P1: scan — edges with dst == N-1 (MLP=4) ============
    if (mode) {
        const long long* __restrict__ srcp = (const long long*)eidx;
        const long long* __restrict__ dstp = srcp + E;
        const int nv = E >> 1;
        const ulonglong2* __restrict__ dv = (const ulonglong2*)dstp;
        const int step = nthreads;
        int i = tid;
        #define P1TEST2(d2, base)                                                              \
            do {                                                                               \
                if ((int)(d2).x == NLAST) { int p = atomicAdd(&g_count1, 1); if (p < CAP1) g_s1[p] = (int)srcp[2*(base)]; }     \
                if ((int)(d2).y == NLAST) { int p = atomicAdd(&g_count1, 1); if (p < CAP1) g_s1[p] = (int)srcp[2*(base)+1]; }   \
            } while (0)
        for (; i + 3 * step < nv; i += 4 * step) {
            ulonglong2 a = dv[i], b = dv[i + step], c = dv[i + 2 * step], d = dv[i + 3 * step];
            P1TEST2(a, i); P1TEST2(b, i + step); P1TEST2(c, i + 2 * step); P1TEST2(d, i + 3 * step);
        }
        for (; i < nv; i += step) { ulonglong2 a = dv[i]; P1TEST2(a, i); }
        for (int e = (nv << 1) + tid; e < E; e += step) {
            if ((int)dstp[e] == NLAST) { int p = atomicAdd(&g_count1, 1); if (p < CAP1) g_s1[p] = (int)srcp[e]; }
        }
        #undef P1TEST2
    } else {
        const int* __restrict__ srcp = (const int*)eidx;
        const int* __restrict__ dstp = srcp + E;
        const int nv = (((unsigned long long)(size_t)dstp & 15ull) == 0ull) ? (E >> 2) : 0;
        const int4* __restrict__ dv = (const int4*)dstp;
        const int step = nthreads;
        int i = tid;
        #define P1TEST4(d4, base)                                                              \
            do {                                                                               \
                if ((d4).x == NLAST) { int p = atomicAdd(&g_count1, 1); if (p < CAP1) g_s1[p] = srcp[4*(base)+0]; }  \
                if ((d4).y == NLAST) { int p = atomicAdd(&g_count1, 1); if (p < CAP1) g_s1[p] = srcp[4*(base)+1]; }  \
                if ((d4).z == NLAST) { int p = atomicAdd(&g_count1, 1); if (p < CAP1) g_s1[p] = srcp[4*(base)+2]; }  \
                if ((d4).w == NLAST) { int p = atomicAdd(&g_count1, 1); if (p < CAP1) g_s1[p] = srcp[4*(base)+3]; }  \
            } while (0)
        for (; i + 3 * step < nv; i += 4 * step) {
            int4 a = dv[i], b = dv[i + step], c = dv[i + 2 * step], d = dv[i + 3 * step];
            P1TEST4(a, i); P1TEST4(b, i + step); P1TEST4(c, i + 2 * step); P1TEST4(d, i + 3 * step);
        }
        for (; i < nv; i += step) { int4 a = dv[i]; P1TEST4(a, i); }
        for (int e = (nv << 2) + tid; e < E; e += step) {
            if (dstp[e] == NLAST) { int p = atomicAdd(&g_count1, 1); if (p < CAP1) g_s1[p] = srcp[e]; }
        }
        #undef P1TEST4
    }
    grid_barrier();   // barrier #1

    // build needed bitmask per-block in smem from g_s1 (~33 entries)
    {
        int c1 = g_count1; if (c1 > CAP1) c1 = CAP1;
        for (int k = threadIdx.x; k < c1; k += TPB) {
            int u = g_s1[k];
            atomicOr(&s_bm[u >> 5], 1u << (u & 31));
        }
        if (threadIdx.x == 0) atomicOr(&s_bm[NLAST >> 5], 1u << (NLAST & 31));
    }
    __syncthreads();

    // ================= P3: scan — edges into needed set (MLP=4) ============
    if (mode) {
        const long long* __restrict__ srcp = (const long long*)eidx;
        const long long* __restrict__ dstp = srcp + E;
        const int nv = E >> 1;
        const ulonglong2* __restrict__ dv = (const ulonglong2*)dstp;
        const int step = nthreads;
        int i = tid;
        #define P3TEST2(d2, base)                                                              \
            do {                                                                               \
                int d0 = (int)(d2).x, d1 = (int)(d2).y;                                        \
                if (BM_TEST(s_bm, d0)) { int s = (int)srcp[2*(base)];   int p = atomicAdd(&g_count2, 1); if (p < CAP2) { g_pair_src[p] = s; g_pair_dst[p] = d0; } } \
                if (BM_TEST(s_bm, d1)) { int s = (int)srcp[2*(base)+1]; int p = atomicAdd(&g_count2, 1); if (p < CAP2) { g_pair_src[p] = s; g_pair_dst[p] = d1; } } \
            } while (0)
        for (; i + 3 * step < nv; i += 4 * step) {
            ulonglong2 a = dv[i], b = dv[i + step], c = dv[i + 2 * step], d = dv[i + 3 * step];
            P3TEST2(a, i); P3TEST2(b, i + step); P3TEST2(c, i + 2 * step); P3TEST2(d, i + 3 * step);
        }
        for (; i < nv; i += step) { ulonglong2 a = dv[i]; P3TEST2(a, i); }
        for (int e = (nv << 1) + tid; e < E; e += step) {
            int d = (int)dstp[e];
            if (BM_TEST(s_bm, d)) { int s = (int)srcp[e]; int p = atomicAdd(&g_count2, 1); if (p < CAP2) { g_pair_src[p] = s; g_pair_dst[p] = d; } }
        }
        #undef P3TEST2
    } else {
        const int* __restrict__ srcp = (const int*)eidx;
        const int* __restrict__ dstp = srcp + E;
        const int nv = (((unsigned long long)(size_t)dstp & 15ull) == 0ull) ? (E >> 2) : 0;
        const int4* __restrict__ dv = (const int4*)dstp;
        const int step = nthreads;
        int i = tid;
        #define P3TEST4(d4, base)                                                              \
            do {                                                                               \
                if (BM_TEST(s_bm, (d4).x)) { int s = srcp[4*(base)+0]; int p = atomicAdd(&g_count2, 1); if (p < CAP2) { g_pair_src[p] = s; g_pair_dst[p] = (d4).x; } } \
                if (BM_TEST(s_bm, (d4).y)) { int s = srcp[4*(base)+1]; int p = atomicAdd(&g_count2, 1); if (p < CAP2) { g_pair_src[p] = s; g_pair_dst[p] = (d4).y; } } \
                if (BM_TEST(s_bm, (d4).z)) { int s = srcp[4*(base)+2]; int p = atomicAdd(&g_count2, 1); if (p < CAP2) { g_pair_src[p] = s; g_pair_dst[p] = (d4).z; } } \
                if (BM_TEST(s_bm, (d4).w)) { int s = srcp[4*(base)+3]; int p = atomicAdd(&g_count2, 1); if (p < CAP2) { g_pair_src[p] = s; g_pair_dst[p] = (d4).w; } } \
            } while (0)
        for (; i + 3 * step < nv; i += 4 * step) {
            int4 a = dv[i], b = dv[i + step], c = dv[i + 2 * step], d = dv[i + 3 * step];
            P3TEST4(a, i); P3TEST4(b, i + step); P3TEST4(c, i + 2 * step); P3TEST4(d, i + 3 * step);
        }
        for (; i < nv; i += step) { int4 a = dv[i]; P3TEST4(a, i); }
        for (int e = (nv << 2) + tid; e < E; e += step) {
            int d = dstp[e];
            if (BM_TEST(s_bm, d)) { int s = srcp[e]; int p = atomicAdd(&g_count2, 1); if (p < CAP2) { g_pair_src[p] = s; g_pair_dst[p] = d; } }
        }
        #undef P3TEST4
    }
    grid_barrier();   // barrier #2

    // extend bitmask with pair srcs → need_deg set
    {
        int c2 = g_count2; if (c2 > CAP2) c2 = CAP2;
        for (int k = threadIdx.x; k < c2; k += TPB) {
            int u = g_pair_src[k];
            atomicOr(&s_bm[u >> 5], 1u << (u & 31));
        }
    }
    __syncthreads();

    // ================= P4: filtered degree scan (MLP=4) ====================
    if (mode) {
        const long long* __restrict__ dstp = (const long long*)eidx + E;
        const int nv = E >> 1;
        const ulonglong2* __restrict__ dv = (const ulonglong2*)dstp;
        const int step = nthreads;
        int i = tid;
        #define P4TEST2(d2)                                                                    \
            do {                                                                               \
                int d0 = (int)(d2).x, d1 = (int)(d2).y;                                        \
                if (BM_TEST(s_bm, d0)) atomicAdd(&g_deg[d0], 1);                               \
                if (BM_TEST(s_bm, d1)) atomicAdd(&g_deg[d1], 1);                               \
            } while (0)
        for (; i + 3 * step < nv; i += 4 * step) {
            ulonglong2 a = dv[i], b = dv[i + step], c = dv[i + 2 * step], d = dv[i + 3 * step];
            P4TEST2(a); P4TEST2(b); P4TEST2(c); P4TEST2(d);
        }
        for (; i < nv; i += step) { ulonglong2 a = dv[i]; P4TEST2(a); }
        for (int e = (nv << 1) + tid; e < E; e += step) {
            int d = (int)dstp[e];
            if (BM_TEST(s_bm, d)) atomicAdd(&g_deg[d], 1);
        }
        #undef P4TEST2
    } else {
        const int* __restrict__ dstp = (const int*)eidx + E;
        const int nv = (((unsigned long long)(size_t)dstp & 15ull) == 0ull) ? (E >> 2) : 0;
        const int4* __restrict__ dv = (const int4*)dstp;
        const int step = nthreads;
        int i = tid;
        #define P4TEST4(d4)                                                                    \
            do {                                                                               \
                if (BM_TEST(s_bm, (d4).x)) atomicAdd(&g_deg[(d4).x], 1);                       \
                if (BM_TEST(s_bm, (d4).y)) atomicAdd(&g_deg[(d4).y], 1);                       \
                if (BM_TEST(s_bm, (d4).z)) atomicAdd(&g_deg[(d4).z], 1);                       \
                if (BM_TEST(s_bm, (d4).w)) atomicAdd(&g_deg[(d4).w], 1);                       \
            } while (0)
        for (; i + 3 * step < nv; i += 4 * step) {
            int4 a = dv[i], b = dv[i + step], c = dv[i + 2 * step], d = dv[i + 3 * step];
            P4TEST4(a); P4TEST4(b); P4TEST4(c); P4TEST4(d);
        }
        for (; i < nv; i += step) { int4 a = dv[i]; P4TEST4(a); }
        for (int e = (nv << 2) + tid; e < E; e += step) {
            int d = dstp[e];
            if (BM_TEST(s_bm, d)) atomicAdd(&g_deg[d], 1);
        }
        #undef P4TEST4
    }
    grid_barrier();   // barrier #3 (last) — blocks != 0 exit after this

    // ================= P5+P6+cleanup: block 0 only =========================
    if (blockIdx.x == 0) {
        int c1 = g_count1; if (c1 > CAP1) c1 = CAP1;
        int c2 = g_count2; if (c2 > CAP2) c2 = CAP2;

        // P5: layer-1 aggregation over pairs (atomics to L2; ~1 per thread)
        for (int k = threadIdx.x; k < c2; k += TPB) {
            int s = g_pair_src[k];
            int d = g_pair_dst[k];
            float dis = rsqrtf((float)(__ldcg(&g_deg[s]) + 1));
            float did = rsqrtf((float)(__ldcg(&g_deg[d]) + 1));
            atomicAdd(&g_s[d], x[s] * dis * did);
        }
        __syncthreads();
        __threadfence();

        // P6: layer-2 @ node N-1 + fc head (warp 0)
        if (threadIdx.x < 32) {
            int lane = threadIdx.x;
            __shared__ float sW1[16], sb1[16], sW2[128], sb2[8], sWfc[8];
            if (lane < 16) { sW1[lane] = W1[lane]; sb1[lane] = b1[lane]; }
            if (lane < 8)  { sb2[lane] = b2[lane]; sWfc[lane] = Wfc[lane]; }
            for (int k = lane; k < 128; k += 32) sW2[k] = W2[k];
            __syncwarp();

            const float dinvL = rsqrtf((float)(__ldcg(&g_deg[NLAST]) + 1));

            float agg[8];
            #pragma unroll
            for (int j = 0; j < 8; j++) agg[j] = 0.0f;

            // k in [0, c1): real edges into N-1; k == c1: appended self-loop.
            for (int k = lane; k <= c1; k += 32) {
                int u = (k == c1) ? NLAST : g_s1[k];
                float du = rsqrtf((float)(__ldcg(&g_deg[u]) + 1));
                float norm = du * dinvL;
                float su = __ldcg(&g_s[u]) + x[u] * du * du;
                float h1[16];
                #pragma unroll
                for (int j = 0; j < 16; j++)
                    h1[j] = fmaxf(fmaf(su, sW1[j], sb1[j]), 0.0f);
                #pragma unroll
                for (int j = 0; j < 8; j++) {
                    float v = 0.0f;
                    #pragma unroll
                    for (int t = 0; t < 16; t++) v = fmaf(h1[t], sW2[t * 8 + j], v);
                    agg[j] = fmaf(v, norm, agg[j]);
                }
            }
            #pragma unroll
            for (int off = 16; off > 0; off >>= 1) {
                #pragma unroll
                for (int j = 0; j < 8; j++)
                    agg[j] += __shfl_down_sync(0xffffffff, agg[j], off);
            }
            if (lane == 0) {
                float o = bfc[0];
                #pragma unroll
                for (int j = 0; j < 8; j++) {
                    float h2 = fmaxf(agg[j] + sb2[j], 0.0f);
                    o = fmaf(h2, sWfc[j], o);
                }
                out[0] = o;
            }
        }
        __syncthreads();

        // cleanup: restore all touched scratch to zero for the next replay.
        // touched set: {s1} ∪ {pair_src} ∪ {pair_dst} ∪ {NLAST}
        for (int k = threadIdx.x; k < c1; k += TPB) {
            int u = g_s1[k];
            g_deg[u] = 0; g_s[u] = 0.0f;
        }
        for (int k = threadIdx.x; k < c2; k += TPB) {
            int s = g_pair_src[k], d = g_pair_dst[k];
            g_deg[s] = 0; g_s[s] = 0.0f;
            g_deg[d] = 0; g_s[d] = 0.0f;
        }
        if (threadIdx.x == 0) {
            g_deg[NLAST] = 0; g_s[NLAST] = 0.0f;
            g_count1 = 0; g_count2 = 0;
        }
    }
}

// ---------------------------------------------------------------------------
extern "C" void kernel_launch(void* const* d_in, const int* in_sizes, int n_in,
                              void* d_out, int out_size) {
    const float* x    = (const float*)d_in[0];
    const void*  eidx = d_in[1];
    const float* W1   = (const float*)d_in[2];
    const float* b1   = (const float*)d_in[3];
    const float* W2   = (const float*)d_in[4];
    const float* b2   = (const float*)d_in[5];
    const float* Wfc  = (const float*)d_in[6];
    const float* bfc  = (const float*)d_in[7];
    float* out = (float*)d_out;

    int E = in_sizes[1] / 2;

    gcn_fused_kernel<<<GRID, TPB>>>(eidx, x, W1, b1, W2, b2, Wfc, bfc, out, E);
}